// round 17
// baseline (speedup 1.0000x reference)
#include <cuda_runtime.h>
#include <math.h>

// Problem constants (fixed by the dataset)
#define NN 8192          // atoms
#define NB 32            // graphs
#define NH 64            // hidden
#define NK 729           // 9^3 lattice points

#define TWO_PI  6.28318530717958647692f
#define FOUR_PI 12.5663706143591729539f

// half-space: lines 40..80 (m_i>0, or m_i==0 && m_j>0, plus (0,0,*) masked to m_z>0)
#define NLINES   41
#define NW_ITEMS (NB * NLINES * 9)     // 11808
#define NMLPB    (NW_ITEMS / 32)       // 369 MLP blocks (32 items x 2 threads)
#define NZB      (NN / 256)            // 32 zero blocks (64 thr x float4)
#define NPROD    (NMLPB + NZB)         // 401 producer blocks (FIRST in grid)
#define NCONS    (NB * NLINES)         // 1312 consumer blocks

typedef unsigned long long u64;

// -------- device scratch (no allocations allowed) --------
__device__ float g_w[NB][NK];
__device__ int   g_prod_done = 0;
__device__ int   g_cons_done = 0;

// ---------------- packed f32x2 helpers ----------------
__device__ __forceinline__ u64 pk2(float lo, float hi) {
    u64 r; asm("mov.b64 %0,{%1,%2};" : "=l"(r) : "f"(lo), "f"(hi)); return r;
}
__device__ __forceinline__ void upk2(u64 v, float& lo, float& hi) {
    asm("mov.b64 {%0,%1},%2;" : "=f"(lo), "=f"(hi) : "l"(v));
}
__device__ __forceinline__ u64 f2fma(u64 a, u64 b, u64 c) {
    u64 d; asm("fma.rn.f32x2 %0,%1,%2,%3;" : "=l"(d) : "l"(a), "l"(b), "l"(c)); return d;
}
__device__ __forceinline__ u64 f2add(u64 a, u64 b) {
    u64 d; asm("add.rn.f32x2 %0,%1,%2;" : "=l"(d) : "l"(a), "l"(b)); return d;
}
__device__ __forceinline__ u64 f2mul(u64 a, u64 b) {
    u64 d; asm("mul.rn.f32x2 %0,%1,%2;" : "=l"(d) : "l"(a), "l"(b)); return d;
}
__device__ __forceinline__ u64 shx64(u64 v, int m) {
    return __shfl_xor_sync(0xffffffffu, v, m);
}

// ---------------------------------------------------------------------------
// 3x3 inverse (double precision). Returns det.
// ---------------------------------------------------------------------------
__device__ __forceinline__ double inv3x3(const float* c, float* o)
{
    double a = c[0], b = c[1], cc = c[2];
    double d = c[3], e = c[4], f  = c[5];
    double g = c[6], h = c[7], i  = c[8];
    double A  = e * i - f * h;
    double Bv = f * g - d * i;
    double C  = d * h - e * g;
    double det = a * A + b * Bv + cc * C;
    double id = 1.0 / det;
    o[0] = (float)(A * id);
    o[1] = (float)((cc * h - b * i) * id);
    o[2] = (float)((b * f - cc * e) * id);
    o[3] = (float)(Bv * id);
    o[4] = (float)((a * i - cc * g) * id);
    o[5] = (float)((cc * d - a * f) * id);
    o[6] = (float)(C * id);
    o[7] = (float)((b * g - a * h) * id);
    o[8] = (float)((a * e - b * d) * id);
    return det;
}

__device__ __forceinline__ float silu(float a) {
    return __fdividef(a, 1.0f + __expf(-a));
}

// ---------------------------------------------------------------------------
// Build the 9 packed phases P[z] = c1 * z^(z-4); chain depth 2, conj symmetry.
// ---------------------------------------------------------------------------
__device__ __forceinline__ void build_phases(
    float c1r, float c1i, float z1r, float z1i, u64* P)
{
    float z2r = z1r * z1r - z1i * z1i, z2i = 2.0f * z1r * z1i;
    float z3r = z2r * z1r - z2i * z1i, z3i = fmaf(z2r, z1i, z2i * z1r);
    float z4r = z2r * z2r - z2i * z2i, z4i = 2.0f * z2r * z2i;
    P[4] = pk2(c1r, c1i);
    {
        float t1 = c1r * z1r, t2 = c1i * z1i, t3 = c1r * z1i, t4 = c1i * z1r;
        P[5] = pk2(t1 - t2, t3 + t4);
        P[3] = pk2(t1 + t2, t4 - t3);
    }
    {
        float t1 = c1r * z2r, t2 = c1i * z2i, t3 = c1r * z2i, t4 = c1i * z2r;
        P[6] = pk2(t1 - t2, t3 + t4);
        P[2] = pk2(t1 + t2, t4 - t3);
    }
    {
        float t1 = c1r * z3r, t2 = c1i * z3i, t3 = c1r * z3i, t4 = c1i * z3r;
        P[7] = pk2(t1 - t2, t3 + t4);
        P[1] = pk2(t1 + t2, t4 - t3);
    }
    {
        float t1 = c1r * z4r, t2 = c1i * z4i, t3 = c1r * z4i, t4 = c1i * z4r;
        P[8] = pk2(t1 - t2, t3 + t4);
        P[0] = pk2(t1 + t2, t4 - t3);
    }
}

// ---------------------------------------------------------------------------
// Single fused kernel. Block roles by blockIdx.x:
//   [0, NMLPB)            : MLP radial filter (2 threads/item, 32 items/block)
//   [NMLPB, NPROD)        : zero the output buffer
//   [NPROD, NPROD+NCONS)  : consumer (graph b, half-space line) energy blocks
// Producers __threadfence + increment g_prod_done. Consumers do pass 1 +
// reduction FIRST, then spin until g_prod_done == NPROD (overlap!), then
// pass 2. Last consumer resets the counters (graph-replay deterministic).
// ---------------------------------------------------------------------------
__global__ void __launch_bounds__(64) k_all(
    const float* __restrict__ pos, const int* __restrict__ batch,
    const float* __restrict__ cell, const float* __restrict__ source,
    const float* __restrict__ W1, const float* __restrict__ B1,
    const float* __restrict__ W2, const float* __restrict__ B2,
    const float* __restrict__ W3, const float* __restrict__ B3,
    float* __restrict__ out)
{
    int bx  = blockIdx.x;
    int tid = threadIdx.x;
    const unsigned FULL = 0xffffffffu;

    if (bx < NMLPB) {
        // =============== MLP producer role (R15-proven math) ===============
        __shared__ float sInv[NB * 9];
        __shared__ __align__(16) float sW2T[NH * 72];
        __shared__ float sW1[3 * NH], sB1[NH], sB2[NH], sW3[NH];

        if (tid < NB) inv3x3(cell + tid * 9, &sInv[tid * 9]);
        for (int idx = tid; idx < 3 * NH; idx += 64) sW1[idx] = W1[idx];
        for (int idx = tid; idx < NH; idx += 64) {
            sB1[idx] = B1[idx]; sB2[idx] = B2[idx]; sW3[idx] = W3[idx];
        }
        for (int idx = tid; idx < NH * NH; idx += 64) {
            int i = idx >> 6, j = idx & 63;
            sW2T[j * 72 + i] = W2[idx];
        }
        __syncthreads();

        int g   = bx * 32 + (tid >> 1);        // always < NW_ITEMS
        int sub = tid & 1;
        int b    = g / (NLINES * 9);
        int rem  = g - b * (NLINES * 9);
        int line = 40 + rem / 9;
        int z    = rem % 9;
        int ki = line / 9 - 4;
        int kj = line % 9 - 4;
        int kk = z - 4;
        const float* iv = &sInv[b * 9];
        float kc0 = TWO_PI * ((float)ki * iv[0] + (float)kj * iv[3] + (float)kk * iv[6]);
        float kc1 = TWO_PI * ((float)ki * iv[1] + (float)kj * iv[4] + (float)kk * iv[7]);
        float kc2 = TWO_PI * ((float)ki * iv[2] + (float)kj * iv[5] + (float)kk * iv[8]);
        float kn = sqrtf(kc0 * kc0 + kc1 * kc1 + kc2 * kc2);

        bool active = (kn > 1e-6f) && !(line == 40 && z < 4);
        float safe = fmaxf(kn, 1e-6f);
        float x0 = log1pf(safe);
        float f0 = x0, f1 = x0 * x0, f2 = 1.0f / safe;

        u64 h1p[NH / 2];
        #pragma unroll
        for (int j = 0; j < NH; j += 2) {
            float a0 = fmaf(f0, sW1[j],     fmaf(f1, sW1[NH + j],     fmaf(f2, sW1[2 * NH + j],     sB1[j])));
            float a1 = fmaf(f0, sW1[j + 1], fmaf(f1, sW1[NH + j + 1], fmaf(f2, sW1[2 * NH + j + 1], sB1[j + 1])));
            h1p[j >> 1] = pk2(silu(a0), silu(a1));
        }

        float o_part = 0.0f;
        int j0 = sub * 32;
        for (int jj = 0; jj < 32; jj++) {
            int j = j0 + jj;
            const ulonglong2* wr = (const ulonglong2*)&sW2T[j * 72];
            u64 acc0 = pk2(sB2[j], 0.0f);
            u64 acc1 = 0ULL;
            #pragma unroll
            for (int i2 = 0; i2 < 16; i2++) {
                ulonglong2 wv = wr[i2];
                acc0 = f2fma(h1p[2 * i2],     wv.x, acc0);
                acc1 = f2fma(h1p[2 * i2 + 1], wv.y, acc1);
            }
            float p0, p1, q0, q1;
            upk2(acc0, p0, p1); upk2(acc1, q0, q1);
            float a = (p0 + p1) + (q0 + q1);
            o_part = fmaf(silu(a), sW3[j], o_part);
        }
        o_part += __shfl_xor_sync(FULL, o_part, 1);
        float o = o_part + B3[0];
        float sp = (o > 80.0f) ? o : log1pf(__expf(o));
        float w = active ? (FOUR_PI / (safe * safe)) * sp : 0.0f;
        if (sub == 0) g_w[b][line * 9 + z] = w;

        // signal
        __threadfence();
        __syncthreads();
        if (tid == 0) atomicAdd(&g_prod_done, 1);
        return;
    }

    if (bx < NPROD) {
        // =============== zero-output producer role ===============
        int n0 = (bx - NMLPB) * 256;
        ((float4*)(out + n0))[tid] = make_float4(0.f, 0.f, 0.f, 0.f);
        __threadfence();
        __syncthreads();
        if (tid == 0) atomicAdd(&g_prod_done, 1);
        return;
    }

    // =============== consumer role ===============
    __shared__ u64 sS[2][36];
    __shared__ float sIv[9];
    __shared__ float sVinv;

    int q    = bx - NPROD;
    int b    = q / NLINES;
    int line = 40 + (q - b * NLINES);
    int w    = tid >> 5;
    int lane = tid & 31;
    int i4 = line / 9, j4 = line % 9;

    // thread 0: inverse cell + volume (fp64) into shared
    if (tid == 0) {
        double det = inv3x3(cell + b * 9, sIv);
        double vol = fabs(det);
        if (vol < 1e-6) vol = 1e-6;
        sVinv = (float)(1.0 / vol);
    }

    // segment offsets via 2-round ballot search (per-warp, redundant)
    int start, end;
    {
        int sv = __ldg(batch + lane * 256);
        unsigned mlo = __ballot_sync(FULL, sv < b);
        unsigned mhi = __ballot_sync(FULL, sv < b + 1);
        int clo = __popc(mlo), chi = __popc(mhi);
        int wlo = (clo == 0) ? 0 : (clo - 1) * 256;
        int whi = (chi == 0) ? 0 : (chi - 1) * 256;
        int cl = 0, ch = 0;
        #pragma unroll
        for (int j = 0; j < 8; j++) {
            cl += (__ldg(batch + wlo + lane * 8 + j) < b)     ? 1 : 0;
            ch += (__ldg(batch + whi + lane * 8 + j) < b + 1) ? 1 : 0;
        }
        start = wlo + __reduce_add_sync(FULL, cl);
        end   = whi + __reduce_add_sync(FULL, ch);
    }
    __syncthreads();

    float mi = (float)(i4 - 4), mj = (float)(j4 - 4);
    float u0 = TWO_PI * (mi * sIv[0] + mj * sIv[1]);
    float u1 = TWO_PI * (mi * sIv[3] + mj * sIv[4]);
    float u2 = TWO_PI * (mi * sIv[6] + mj * sIv[7]);
    float v0 = TWO_PI * sIv[2], v1 = TWO_PI * sIv[5], v2 = TWO_PI * sIv[8];

    const float4* __restrict__ SRC = (const float4*)source;

    u64 acc[36];
    #pragma unroll
    for (int v = 0; v < 36; v++) acc[v] = 0ULL;

    // ---- pass 1: structure factors ----
    {
        int a = start + lane + 32 * w;
        float Lx, Ly, Lz; float4 LSV;
        if (a < end) {
            Lx = __ldg(pos + 3 * a); Ly = __ldg(pos + 3 * a + 1); Lz = __ldg(pos + 3 * a + 2);
            LSV = SRC[a];
        }
        while (a < end) {
            float px = Lx, py = Ly, pz = Lz; float4 sv = LSV;
            int an = a + 64;
            if (an < end) {
                Lx = __ldg(pos + 3 * an); Ly = __ldg(pos + 3 * an + 1); Lz = __ldg(pos + 3 * an + 2);
                LSV = SRC[an];
            }
            float th1 = fmaf(px, u0, fmaf(py, u1, pz * u2));
            float thz = fmaf(px, v0, fmaf(py, v1, pz * v2));
            float c1r, c1i, z1r, z1i;
            __sincosf(th1, &c1i, &c1r);
            __sincosf(thz, &z1i, &z1r);
            u64 P[9];
            build_phases(c1r, c1i, z1r, z1i, P);
            u64 s0 = pk2(sv.x, sv.x), s1 = pk2(sv.y, sv.y);
            u64 s2 = pk2(sv.z, sv.z), s3 = pk2(sv.w, sv.w);
            #pragma unroll
            for (int z = 0; z < 9; z++) {
                acc[z * 4 + 0] = f2fma(s0, P[z], acc[z * 4 + 0]);
                acc[z * 4 + 1] = f2fma(s1, P[z], acc[z * 4 + 1]);
                acc[z * 4 + 2] = f2fma(s2, P[z], acc[z * 4 + 2]);
                acc[z * 4 + 3] = f2fma(s3, P[z], acc[z * 4 + 3]);
            }
            a = an;
        }
    }

    // ---- distributed exchange reduce: lane l ends with value l ----
    #pragma unroll
    for (int o = 16; o >= 1; o >>= 1) {
        bool hi = (lane & o) != 0;
        #pragma unroll
        for (int j = 0; j < o; j++) {
            u64 tlo = shx64(acc[j],     o);
            u64 thi = shx64(acc[j + o], o);
            acc[j] = hi ? f2add(acc[j + o], thi) : f2add(acc[j], tlo);
        }
    }
    sS[w][lane] = acc[0];
    #pragma unroll
    for (int o = 16; o; o >>= 1) {
        acc[32] = f2add(acc[32], shx64(acc[32], o));
        acc[33] = f2add(acc[33], shx64(acc[33], o));
        acc[34] = f2add(acc[34], shx64(acc[34], o));
        acc[35] = f2add(acc[35], shx64(acc[35], o));
    }
    if (lane < 4) {
        u64 qv = (lane == 0) ? acc[32] : (lane == 1) ? acc[33]
               : (lane == 2) ? acc[34] : acc[35];
        sS[w][32 + lane] = qv;
    }

    // ---- wait for producers (overlapped: only here is g_w needed) ----
    if (tid == 0) {
        while (*((volatile int*)&g_prod_done) != NPROD) __nanosleep(64);
    }
    __syncthreads();
    __threadfence();   // acquire: order g_w/out reads after the flag

    // ---- combine warps + fold in w(k) ----
    u64 Wp[36];
    #pragma unroll
    for (int z = 0; z < 9; z++) {
        float wzv = g_w[b][line * 9 + z];
        u64 wzp = pk2(wzv, wzv);
        #pragma unroll
        for (int c = 0; c < 4; c++) {
            int v = z * 4 + c;
            Wp[v] = f2mul(wzp, f2add(sS[0][v], sS[1][v]));
        }
    }
    float hv = sVinv;   // 0.5 (energy) x 2 (half-space) = 1

    // ---- pass 2: per-atom energy ----
    {
        int a = start + lane + 32 * w;
        float Lx, Ly, Lz; float4 LSV;
        if (a < end) {
            Lx = __ldg(pos + 3 * a); Ly = __ldg(pos + 3 * a + 1); Lz = __ldg(pos + 3 * a + 2);
            LSV = SRC[a];
        }
        while (a < end) {
            float px = Lx, py = Ly, pz = Lz; float4 sv = LSV;
            int an = a + 64;
            if (an < end) {
                Lx = __ldg(pos + 3 * an); Ly = __ldg(pos + 3 * an + 1); Lz = __ldg(pos + 3 * an + 2);
                LSV = SRC[an];
            }
            float th1 = fmaf(px, u0, fmaf(py, u1, pz * u2));
            float thz = fmaf(px, v0, fmaf(py, v1, pz * v2));
            float c1r, c1i, z1r, z1i;
            __sincosf(th1, &c1i, &c1r);
            __sincosf(thz, &z1i, &z1r);
            u64 P[9];
            build_phases(c1r, c1i, z1r, z1i, P);
            u64 E0 = 0ULL, E1 = 0ULL, E2 = 0ULL, E3 = 0ULL;
            #pragma unroll
            for (int z = 0; z < 9; z++) {
                E0 = f2fma(P[z], Wp[z * 4 + 0], E0);
                E1 = f2fma(P[z], Wp[z * 4 + 1], E1);
                E2 = f2fma(P[z], Wp[z * 4 + 2], E2);
                E3 = f2fma(P[z], Wp[z * 4 + 3], E3);
            }
            float e0a, e0b, e1a, e1b, e2a, e2b, e3a, e3b;
            upk2(E0, e0a, e0b); upk2(E1, e1a, e1b);
            upk2(E2, e2a, e2b); upk2(E3, e3a, e3b);
            float e = sv.x * (e0a + e0b) + sv.y * (e1a + e1b)
                    + sv.z * (e2a + e2b) + sv.w * (e3a + e3b);
            atomicAdd(out + a, hv * e);
            a = an;
        }
    }

    // ---- last consumer resets counters for the next graph replay ----
    __syncthreads();
    if (tid == 0) {
        int r = atomicAdd(&g_cons_done, 1);
        if (r == NCONS - 1) {
            atomicExch(&g_prod_done, 0);
            atomicExch(&g_cons_done, 0);
            __threadfence();
        }
    }
}

// ---------------------------------------------------------------------------
extern "C" void kernel_launch(void* const* d_in, const int* in_sizes, int n_in,
                              void* d_out, int out_size)
{
    const float* pos    = (const float*)d_in[0];
    const int*   batch  = (const int*)d_in[1];
    const float* cell   = (const float*)d_in[2];
    const float* source = (const float*)d_in[3];
    const float* W1 = (const float*)d_in[4];
    const float* B1 = (const float*)d_in[5];
    const float* W2 = (const float*)d_in[6];
    const float* B2 = (const float*)d_in[7];
    const float* W3 = (const float*)d_in[8];
    const float* B3 = (const float*)d_in[9];
    float* out = (float*)d_out;

    k_all<<<NPROD + NCONS, 64>>>(pos, batch, cell, source,
                                 W1, B1, W2, B2, W3, B3, out);
}